// round 8
// baseline (speedup 1.0000x reference)
#include <cuda_runtime.h>

// SlidingVariance: x (B=32, L=16384, C=1) fp32, w=64.
// out[b,i] = population variance of x[b, i : min(i+w, L)].
//
// Barrier-free, smem-free warp-autonomous kernel. Each warp stages 256
// elements in registers (8/lane as two float4), computes per-lane local
// prefixes of (x, x^2), warp-scans the lane totals, then pulls lane l+8's
// prefix state down via shfl (64 elements = 8 lanes ahead):
//   windowsum(o=8l+k) = [Es(l+8)-Es(l)] + [lsk(l+8)-lsk(l)]
// Lanes 0..23 each emit 8 outputs -> 192 outputs per warp. No syncthreads.

#define W  64

__global__ __launch_bounds__(256)
void sliding_var_kernel(const float* __restrict__ x,
                        float* __restrict__ out,
                        int L) {
    const int b    = blockIdx.y;
    const int wid  = threadIdx.x >> 5;
    const int lane = threadIdx.x & 31;

    const int o0 = (blockIdx.x * 8 + wid) * 192;   // warp's first output
    if (o0 >= L) return;

    const float* xb = x + (long)b * L;
    const int idx = o0 + lane * 8;

    // ---- Stage 8 elements (two float4), zero past L ----
    float4 a, c;
    if (o0 + 256 <= L) {
        const float4* p = reinterpret_cast<const float4*>(xb + idx);
        a = p[0];
        c = p[1];
    } else {
        const float z = 0.0f;
        a.x = (idx + 0 < L) ? xb[idx + 0] : z;
        a.y = (idx + 1 < L) ? xb[idx + 1] : z;
        a.z = (idx + 2 < L) ? xb[idx + 2] : z;
        a.w = (idx + 3 < L) ? xb[idx + 3] : z;
        c.x = (idx + 4 < L) ? xb[idx + 4] : z;
        c.y = (idx + 5 < L) ? xb[idx + 5] : z;
        c.z = (idx + 6 < L) ? xb[idx + 6] : z;
        c.w = (idx + 7 < L) ? xb[idx + 7] : z;
    }

    // ---- Local inclusive prefixes ls[k], lq[k] (k = 0..7) ----
    float ls[8], lq[8];
    ls[0] = a.x;         lq[0] = a.x * a.x;
    ls[1] = ls[0] + a.y; lq[1] = fmaf(a.y, a.y, lq[0]);
    ls[2] = ls[1] + a.z; lq[2] = fmaf(a.z, a.z, lq[1]);
    ls[3] = ls[2] + a.w; lq[3] = fmaf(a.w, a.w, lq[2]);
    ls[4] = ls[3] + c.x; lq[4] = fmaf(c.x, c.x, lq[3]);
    ls[5] = ls[4] + c.y; lq[5] = fmaf(c.y, c.y, lq[4]);
    ls[6] = ls[5] + c.z; lq[6] = fmaf(c.z, c.z, lq[5]);
    ls[7] = ls[6] + c.w; lq[7] = fmaf(c.w, c.w, lq[6]);

    // ---- Warp inclusive scan of lane totals -> exclusive Es, Eq ----
    float scan_s = ls[7], scan_q = lq[7];
    #pragma unroll
    for (int o = 1; o < 32; o <<= 1) {
        float as = __shfl_up_sync(0xFFFFFFFFu, scan_s, o);
        float aq = __shfl_up_sync(0xFFFFFFFFu, scan_q, o);
        if (lane >= o) { scan_s += as; scan_q += aq; }
    }
    const float Es = scan_s - ls[7];
    const float Eq = scan_q - lq[7];

    // ---- Pull lane l+8's prefix state (64 elements ahead) ----
    const float Es8 = __shfl_down_sync(0xFFFFFFFFu, Es, 8);
    const float Eq8 = __shfl_down_sync(0xFFFFFFFFu, Eq, 8);
    float hs[8], hq[8];
    #pragma unroll
    for (int k = 0; k < 8; k++) {
        hs[k] = __shfl_down_sync(0xFFFFFFFFu, ls[k], 8);
        hq[k] = __shfl_down_sync(0xFFFFFFFFu, lq[k], 8);
    }

    if (lane >= 24) return;          // no outputs for top 8 lanes
    const int i = o0 + lane * 8;     // first output index (mult of 8)
    if (i >= L) return;

    // windowsum(k) = (Es8 + hs[k-1]) - (Es + ls[k-1]); k=0 uses 0.
    const float dS = Es8 - Es;
    const float dQ = Eq8 - Eq;
    float sw[8], qw[8];
    sw[0] = dS;
    qw[0] = dQ;
    #pragma unroll
    for (int k = 1; k < 8; k++) {
        sw[k] = dS + (hs[k - 1] - ls[k - 1]);
        qw[k] = dQ + (hq[k - 1] - lq[k - 1]);
    }

    float4 r0, r1;
    float* ro = reinterpret_cast<float*>(&r0);   // r0,r1 contiguous
    float* r4 = reinterpret_cast<float*>(&r1);
    if (i + 7 + W <= L) {
        const float inv = 1.0f / (float)W;
        #pragma unroll
        for (int k = 0; k < 4; k++) {
            float m = sw[k] * inv;
            ro[k] = fmaf(-m, m, qw[k] * inv);
        }
        #pragma unroll
        for (int k = 0; k < 4; k++) {
            float m = sw[k + 4] * inv;
            r4[k] = fmaf(-m, m, qw[k + 4] * inv);
        }
    } else {
        #pragma unroll
        for (int k = 0; k < 8; k++) {
            int n = min(W, L - (i + k));   // i+k < L (L % 8 == 0)
            float invn = 1.0f / (float)n;
            float m = sw[k] * invn;
            float val = fmaf(-m, m, qw[k] * invn);
            if (k < 4) ro[k] = val; else r4[k - 4] = val;
        }
    }

    float4* op = reinterpret_cast<float4*>(out + (long)b * L + i);
    op[0] = r0;
    op[1] = r1;
}

extern "C" void kernel_launch(void* const* d_in, const int* in_sizes, int n_in,
                              void* d_out, int out_size) {
    const float* x = (const float*)d_in[0];
    float* out = (float*)d_out;

    const int B = 32;
    const int L = 16384;

    // 86 warps per row (85*192 = 16320, last warp covers the tail),
    // 8 warps per block -> 11 blocks per row.
    dim3 grid(11, B);
    sliding_var_kernel<<<grid, 256>>>(x, out, L);
}